// round 5
// baseline (speedup 1.0000x reference)
#include <cuda_runtime.h>
#include <cuda_fp16.h>
#include <cstdint>
#include <cstddef>

// ---------------------------------------------------------------------------
// Device scratch: fp16-rounded folded weight and fp16-rounded x.
// ---------------------------------------------------------------------------
static __device__ __half g_Wh[4096ull * 4096ull];   // 32 MB
static __device__ __half g_Xh[8192ull * 4096ull];   // 64 MB

__device__ __forceinline__ uint32_t smem_u32(const void* p) {
    uint32_t a;
    asm("{ .reg .u64 t; cvta.to.shared.u64 t, %1; cvt.u32.u64 %0, t; }"
        : "=r"(a) : "l"(p));
    return a;
}

#define CP16(dst, src) \
    asm volatile("cp.async.cg.shared.global [%0], [%1], 16;" \
                 :: "r"(dst), "l"(src) : "memory")
#define CP_COMMIT() asm volatile("cp.async.commit_group;" ::: "memory")
#define CP_WAIT1()  asm volatile("cp.async.wait_group 1;" ::: "memory")

#define LDSM4(r, addr) \
    asm volatile("ldmatrix.sync.aligned.m8n8.x4.shared.b16 {%0,%1,%2,%3}, [%4];" \
                 : "=r"((r)[0]), "=r"((r)[1]), "=r"((r)[2]), "=r"((r)[3]) \
                 : "r"(addr))

#define MMA16816(c, a, b0, b1) \
    asm volatile("mma.sync.aligned.m16n8k16.row.col.f32.f16.f16.f32 " \
                 "{%0,%1,%2,%3},{%4,%5,%6,%7},{%8,%9},{%0,%1,%2,%3};" \
                 : "+f"((c)[0]), "+f"((c)[1]), "+f"((c)[2]), "+f"((c)[3]) \
                 : "r"((a)[0]), "r"((a)[1]), "r"((a)[2]), "r"((a)[3]), \
                   "r"(b0), "r"(b1))

// ---------------------------------------------------------------------------
// Kernel 0: g_Xh = fp16_rn(x).
// ---------------------------------------------------------------------------
__global__ void xround_kernel(const float* __restrict__ x) {
    const size_t i = (size_t)blockIdx.x * blockDim.x + threadIdx.x;
    const float4 v0 = reinterpret_cast<const float4*>(x)[2 * i];
    const float4 v1 = reinterpret_cast<const float4*>(x)[2 * i + 1];
    __half2 h[4];
    h[0] = __floats2half2_rn(v0.x, v0.y);
    h[1] = __floats2half2_rn(v0.z, v0.w);
    h[2] = __floats2half2_rn(v1.x, v1.y);
    h[3] = __floats2half2_rn(v1.z, v1.w);
    reinterpret_cast<uint4*>(g_Xh)[i] = *reinterpret_cast<uint4*>(h);
}

// ---------------------------------------------------------------------------
// Kernel 1: g_Wh[o,i] = fp16_rn( W[o,i] + 2 * sum_r B[o,r] * A[r,i] )
// ---------------------------------------------------------------------------
__global__ void weff_kernel(const float* __restrict__ W,
                            const float* __restrict__ A,
                            const float* __restrict__ B) {
    __shared__ float As[16][128];
    __shared__ float Bsh[32][16];
    const int o0 = blockIdx.y * 32;
    const int i0 = blockIdx.x * 128;
    const int tid = threadIdx.x;

    for (int idx = tid; idx < 16 * 32; idx += 256) {
        const int r = idx >> 5, c = idx & 31;
        reinterpret_cast<float4*>(&As[r][0])[c] =
            reinterpret_cast<const float4*>(A + r * 4096 + i0)[c];
    }
    for (int idx = tid; idx < 32 * 16; idx += 256) {
        const int r = idx >> 4, c = idx & 15;
        Bsh[r][c] = B[(size_t)(o0 + r) * 16 + c];
    }
    __syncthreads();

    const int tx = tid & 31;
    const int ty = tid >> 5;
    #pragma unroll
    for (int j = 0; j < 4; j++) {
        const int ol = ty + 8 * j;
        const size_t off = (size_t)(o0 + ol) * 4096 + i0;
        const float4 w = reinterpret_cast<const float4*>(W + off)[tx];
        float4 acc = make_float4(0.f, 0.f, 0.f, 0.f);
        #pragma unroll
        for (int r = 0; r < 16; r++) {
            const float br = Bsh[ol][r];
            const float4 a = reinterpret_cast<const float4*>(&As[r][0])[tx];
            acc.x += br * a.x; acc.y += br * a.y;
            acc.z += br * a.z; acc.w += br * a.w;
        }
        __half2 h0 = __floats2half2_rn(w.x + 2.f * acc.x, w.y + 2.f * acc.y);
        __half2 h1 = __floats2half2_rn(w.z + 2.f * acc.z, w.w + 2.f * acc.w);
        uint2 o;
        o.x = *reinterpret_cast<uint32_t*>(&h0);
        o.y = *reinterpret_cast<uint32_t*>(&h1);
        reinterpret_cast<uint2*>(g_Wh + off)[tx] = o;
    }
}

// ---------------------------------------------------------------------------
// Kernel 2: fp16 tensor GEMM.  out[m,n] = sum_k Xh[m,k]*Wh[n,k] + bias[n]
// CTA tile 128(M) x 256(N) x 64(K)/stage, 3-stage cp.async pipeline.
// 512 threads / 16 warps (2m x 8n), warp tile 64x32. SW128 + ldmatrix.x4.
// ---------------------------------------------------------------------------
static constexpr int BK      = 64;                 // halves per stage (128B row)
static constexpr int STAGES  = 3;
static constexpr int A_STAGE = 128 * 128;          // bytes
static constexpr int B_STAGE = 256 * 128;          // bytes
static constexpr int SMEM_SZ = STAGES * (A_STAGE + B_STAGE);  // 147456
static constexpr int KT      = 4096 / BK;          // 64
static constexpr int NTHREADS = 512;

__device__ __forceinline__ uint32_t sw_off(int row, int c) {
    return (uint32_t)(row * 128 + ((c ^ (row & 7)) << 4));
}

__global__ __launch_bounds__(NTHREADS, 1)
void gemm_fp16(const float* __restrict__ bias, float* __restrict__ out) {
    extern __shared__ __align__(1024) char smem[];
    const uint32_t sb = smem_u32(smem);
    const uint32_t sA = sb;
    const uint32_t sB = sb + STAGES * A_STAGE;

    const int tid  = threadIdx.x;
    const int lane = tid & 31;
    const int warp = tid >> 5;
    const int wm = (warp >> 3) << 6;   // 0 or 64
    const int wn = (warp & 7) << 5;    // 0..224 step 32
    const int m0 = blockIdx.y << 7;
    const int n0 = blockIdx.x << 8;

    const __half* __restrict__ Xh = g_Xh;
    const __half* __restrict__ Wh = g_Wh;

    float acc[4][4][4];
    #pragma unroll
    for (int i = 0; i < 4; i++)
        #pragma unroll
        for (int j = 0; j < 4; j++)
            #pragma unroll
            for (int q = 0; q < 4; q++) acc[i][j][q] = 0.f;

    auto load_stage = [&](int s, int kt) {
        const int k0 = kt * BK;
        #pragma unroll
        for (int it = 0; it < 2; it++) {          // A: 1024 16B units
            const int u = it * NTHREADS + tid;
            const int row = u >> 3, c = u & 7;
            CP16(sA + s * A_STAGE + sw_off(row, c),
                 Xh + (size_t)(m0 + row) * 4096 + k0 + c * 8);
        }
        #pragma unroll
        for (int it = 0; it < 4; it++) {          // B: 2048 16B units
            const int u = it * NTHREADS + tid;
            const int row = u >> 3, c = u & 7;
            CP16(sB + s * B_STAGE + sw_off(row, c),
                 Wh + (size_t)(n0 + row) * 4096 + k0 + c * 8);
        }
        CP_COMMIT();
    };

    load_stage(0, 0);
    load_stage(1, 1);

    const int arow = lane & 15;
    const int aclo = lane >> 4;

    for (int kt = 0; kt < KT; kt++) {
        CP_WAIT1();
        __syncthreads();
        if (kt + 2 < KT) load_stage((kt + 2) % STAGES, kt + 2);
        else             CP_COMMIT();

        const int buf = kt % STAGES;
        const uint32_t ab = sA + buf * A_STAGE;
        const uint32_t bb = sB + buf * B_STAGE;

        #pragma unroll
        for (int q = 0; q < 4; q++) {             // 4 k16-chunks
            uint32_t ar[4][4], br[2][4];
            #pragma unroll
            for (int fm = 0; fm < 4; fm++)
                LDSM4(ar[fm], ab + sw_off(wm + fm * 16 + arow, q * 2 + aclo));
            #pragma unroll
            for (int j = 0; j < 2; j++)
                LDSM4(br[j], bb + sw_off(wn + j * 16 + arow, q * 2 + aclo));
            #pragma unroll
            for (int fm = 0; fm < 4; fm++)
                #pragma unroll
                for (int j = 0; j < 2; j++) {
                    MMA16816(acc[fm][2 * j],     ar[fm], br[j][0], br[j][2]);
                    MMA16816(acc[fm][2 * j + 1], ar[fm], br[j][1], br[j][3]);
                }
        }
    }

    // Epilogue: direct reg -> gmem with fused bias.
    #pragma unroll
    for (int fm = 0; fm < 4; fm++) {
        const int r0 = m0 + wm + fm * 16 + (lane >> 2);
        #pragma unroll
        for (int fn = 0; fn < 4; fn++) {
            const int col = n0 + wn + fn * 8 + ((lane & 3) << 1);
            const float2 b2 = *reinterpret_cast<const float2*>(bias + col);
            float2 v0 = make_float2(acc[fm][fn][0] + b2.x, acc[fm][fn][1] + b2.y);
            float2 v1 = make_float2(acc[fm][fn][2] + b2.x, acc[fm][fn][3] + b2.y);
            *reinterpret_cast<float2*>(out + (size_t)r0 * 4096 + col) = v0;
            *reinterpret_cast<float2*>(out + (size_t)(r0 + 8) * 4096 + col) = v1;
        }
    }
}

// ---------------------------------------------------------------------------
// Host entry. Inputs: x, W, b, A, B. Output fp32 [8192, 4096].
// ---------------------------------------------------------------------------
extern "C" void kernel_launch(void* const* d_in, const int* in_sizes, int n_in,
                              void* d_out, int out_size) {
    const float* x = (const float*)d_in[0];
    const float* W = (const float*)d_in[1];
    const float* b = (const float*)d_in[2];
    const float* A = (const float*)d_in[3];
    const float* B = (const float*)d_in[4];
    float* out = (float*)d_out;

    static bool attr_done = false;
    if (!attr_done) {
        cudaFuncSetAttribute(gemm_fp16,
                             cudaFuncAttributeMaxDynamicSharedMemorySize, SMEM_SZ);
        attr_done = true;
    }

    xround_kernel<<<8192 * 4096 / 8 / 256, 256>>>(x);
    weff_kernel<<<dim3(32, 128), 256>>>(W, A, B);
    gemm_fp16<<<dim3(16, 64), NTHREADS, SMEM_SZ>>>(b, out);
}